// round 16
// baseline (speedup 1.0000x reference)
#include <cuda_runtime.h>
#include <cuda_bf16.h>
#include <math.h>
#include <stdint.h>

#define NB 2
#define HW 1024
#define LSEQ 1024
#define IN_CHS 512
#define DIM 128
#define D_MODEL 1024
#define D_INNER 2048
#define DT_RANK 64
#define D_STATE 16
#define MROWS (NB*LSEQ)
#define BN_EPS 1e-5f

// ---------------- scratch (allocation-free: device globals) ----------------
__device__ float g_t    [MROWS * DIM];
__device__ float g_y0   [NB * DIM];
__device__ float g_pool9 [NB*IN_CHS*81];
__device__ float g_pool17[NB*IN_CHS*289];
__device__ float g_pool25[NB*IN_CHS*625];
__device__ float g_ppm9 [NB*DIM*81];
__device__ float g_ppm17[NB*DIM*289];
__device__ float g_ppm25[NB*DIM*625];
__device__ float g_xz   [MROWS * 2*D_INNER];
__device__ float g_u    [MROWS * D_INNER];
__device__ float g_xdbl [MROWS * 96];
__device__ float g_delta[MROWS * D_INNER];
__device__ float g_yout [MROWS * D_MODEL];

// bf16 hi/lo pairs for GEMM operands (16B aligned for cp.async)
__device__ __align__(16) uint16_t g_seq_h  [MROWS * D_MODEL];
__device__ __align__(16) uint16_t g_seq_l  [MROWS * D_MODEL];
__device__ __align__(16) uint16_t g_u_h    [MROWS * D_INNER];
__device__ __align__(16) uint16_t g_u_l    [MROWS * D_INNER];
__device__ __align__(16) uint16_t g_xdbl_h [MROWS * 96];
__device__ __align__(16) uint16_t g_xdbl_l [MROWS * 96];
__device__ __align__(16) uint16_t g_yg_h   [MROWS * D_INNER];
__device__ __align__(16) uint16_t g_yg_l   [MROWS * D_INNER];
__device__ __align__(16) uint16_t g_wip_h  [2*D_INNER * D_MODEL];
__device__ __align__(16) uint16_t g_wip_l  [2*D_INNER * D_MODEL];
__device__ __align__(16) uint16_t g_wxp_h  [96 * D_INNER];
__device__ __align__(16) uint16_t g_wxp_l  [96 * D_INNER];
__device__ __align__(16) uint16_t g_wdt_h  [D_INNER * DT_RANK];
__device__ __align__(16) uint16_t g_wdt_l  [D_INNER * DT_RANK];
__device__ __align__(16) uint16_t g_wop_h  [D_MODEL * D_INNER];
__device__ __align__(16) uint16_t g_wop_l  [D_MODEL * D_INNER];
__device__ __align__(16) uint16_t g_wp0_h  [DIM * IN_CHS];
__device__ __align__(16) uint16_t g_wp0_l  [DIM * IN_CHS];

__device__ __forceinline__ void split_store(float v, uint16_t* hi, uint16_t* lo, size_t idx) {
    __nv_bfloat16 h = __float2bfloat16(v);
    hi[idx] = __bfloat16_as_ushort(h);
    lo[idx] = __bfloat16_as_ushort(__float2bfloat16(v - __bfloat162float(h)));
}

// ---------------- small helpers ----------------
__global__ void k_zero(float* p, int n) {
    int t = blockIdx.x * blockDim.x + threadIdx.x;
    if (t < n) p[t] = 0.f;
}

__global__ void k_split(const float* __restrict__ src, uint16_t* __restrict__ hi,
                        uint16_t* __restrict__ lo, int n) {
    int t = blockIdx.x * blockDim.x + threadIdx.x;
    if (t < n) split_store(src[t], hi, lo, t);
}

__global__ void k_x_to_seq(const float* __restrict__ x) {
    int t = blockIdx.x * blockDim.x + threadIdx.x;
    if (t >= NB * HW * IN_CHS) return;
    int c  = t % IN_CHS;
    int hw = (t / IN_CHS) % HW;
    int b  = t / (IN_CHS * HW);
    split_store(x[(size_t)(b * IN_CHS + c) * HW + hw], g_seq_h, g_seq_l,
                (size_t)(b * HW + hw) * D_MODEL + c);
}

// ---------------- tensor-core 3xBF16 GEMM (m16n8k16, ldmatrix, BK=32) ----------------
__device__ __forceinline__ void mma_bf16(float* c, uint32_t a0, uint32_t a1,
                                         uint32_t a2, uint32_t a3,
                                         uint32_t b0, uint32_t b1) {
    asm volatile(
        "mma.sync.aligned.m16n8k16.row.col.f32.bf16.bf16.f32 "
        "{%0,%1,%2,%3}, {%4,%5,%6,%7}, {%8,%9}, {%0,%1,%2,%3};\n"
        : "+f"(c[0]), "+f"(c[1]), "+f"(c[2]), "+f"(c[3])
        : "r"(a0), "r"(a1), "r"(a2), "r"(a3), "r"(b0), "r"(b1));
}
__device__ __forceinline__ void ldsm_x4(uint32_t& r0, uint32_t& r1, uint32_t& r2,
                                        uint32_t& r3, uint32_t addr) {
    asm volatile("ldmatrix.sync.aligned.m8n8.x4.shared.b16 {%0,%1,%2,%3}, [%4];"
                 : "=r"(r0), "=r"(r1), "=r"(r2), "=r"(r3) : "r"(addr));
}
__device__ __forceinline__ void cp_async16(uint32_t smem_addr, const void* gmem) {
    asm volatile("cp.async.cg.shared.global [%0], [%1], 16;\n" :: "r"(smem_addr), "l"(gmem));
}
__device__ __forceinline__ void cp_commit() { asm volatile("cp.async.commit_group;\n"); }
__device__ __forceinline__ void cp_wait1()  { asm volatile("cp.async.wait_group 1;\n"); }

// BK=32: per stage-operand tile 128 rows x 16 words (32 bf16) + 4 pad = 20 words/row
#define SMROW_W 20
#define TSZ_W (128 * SMROW_W)            // 2560 words = 10240 B per operand-stage
#define GEMM_SMEM (8 * TSZ_W * 4)        // 4 operands x 2 stages = 81920 B

// mode: 0 = plain store, 1 = atomicAdd, 2 = store softplus(acc + bias[col])
__global__ __launch_bounds__(256, 2)
void k_gemm_tc(int M, int N, int K, int kchunk, int mode,
               const uint16_t* __restrict__ Ah, const uint16_t* __restrict__ Al, int lda,
               const uint16_t* __restrict__ Bh, const uint16_t* __restrict__ Bl, int ldb,
               float* __restrict__ C, int ldc, const float* __restrict__ bias)
{
    extern __shared__ uint32_t smu[];
    uint32_t* AH = smu;
    uint32_t* AL = smu + 2 * TSZ_W;
    uint32_t* BH = smu + 4 * TSZ_W;
    uint32_t* BL = smu + 6 * TSZ_W;

    int bm = blockIdx.y * 128, bn = blockIdx.x * 128;
    int tid = threadIdx.x, lane = tid & 31, warp = tid >> 5;
    int wm = (warp >> 2) * 64;
    int wn = (warp & 3) * 32;
    int lq = lane >> 2;
    int lr4 = lane & 3;
    int kbeg = blockIdx.z * kchunk;
    int kend = min(K, kbeg + kchunk);

    float acc[4][4][4];
#pragma unroll
    for (int mi = 0; mi < 4; mi++)
#pragma unroll
        for (int ni = 0; ni < 4; ni++)
#pragma unroll
            for (int r = 0; r < 4; r++) acc[mi][ni][r] = 0.f;

    // loader: 2 threads per row; each covers 16 bf16 (2 x 16B chunks)
    int ldr   = tid >> 1;           // 0..127
    int lde16 = (tid & 1) * 16;     // element offset 0 or 16
    int ldw8  = (tid & 1) * 8;      // word offset 0 or 8
    bool bok = (bn + ldr) < N;

    if (!bok) {
#pragma unroll
        for (int st = 0; st < 2; st++)
#pragma unroll
            for (int i = 0; i < 8; i++) {
                BH[st * TSZ_W + ldr * SMROW_W + ldw8 + i] = 0u;
                BL[st * TSZ_W + ldr * SMROW_W + ldw8 + i] = 0u;
            }
    }
    __syncthreads();

    uint32_t aAH = (uint32_t)__cvta_generic_to_shared(&AH[ldr * SMROW_W + ldw8]);
    uint32_t aAL = (uint32_t)__cvta_generic_to_shared(&AL[ldr * SMROW_W + ldw8]);
    uint32_t aBH = (uint32_t)__cvta_generic_to_shared(&BH[ldr * SMROW_W + ldw8]);
    uint32_t aBL = (uint32_t)__cvta_generic_to_shared(&BL[ldr * SMROW_W + ldw8]);
    const uint32_t stB = TSZ_W * 4;          // stage stride in bytes

    // ldmatrix lane offsets (words, within a stage, k-chunk 0)
    int offA = (wm + (lane & 15)) * SMROW_W + ((lane & 16) >> 2);
    int offB = (wn + (lane & 7) + ((lane & 16) >> 1)) * SMROW_W + ((lane & 8) >> 1);

    uint32_t bAHf = (uint32_t)__cvta_generic_to_shared(AH) + offA * 4;
    uint32_t bALf = (uint32_t)__cvta_generic_to_shared(AL) + offA * 4;
    uint32_t bBHf = (uint32_t)__cvta_generic_to_shared(BH) + offB * 4;
    uint32_t bBLf = (uint32_t)__cvta_generic_to_shared(BL) + offB * 4;
    const uint32_t miStep = 16 * SMROW_W * 4;   // bytes per 16 rows

    // prologue: stage 0 (k = kbeg .. kbeg+32)
    {
        size_t ra = (size_t)(bm + ldr) * lda + kbeg + lde16;
        cp_async16(aAH,      Ah + ra);
        cp_async16(aAH + 16, Ah + ra + 4 * 0 + 8);   // second 16B chunk (words +4)
        // NOTE: +16 bytes = +4 words = +8 bf16 elements
        cp_async16(aAL,      Al + ra);
        cp_async16(aAL + 16, Al + ra + 8);
        if (bok) {
            size_t rb = (size_t)(bn + ldr) * ldb + kbeg + lde16;
            cp_async16(aBH,      Bh + rb);
            cp_async16(aBH + 16, Bh + rb + 8);
            cp_async16(aBL,      Bl + rb);
            cp_async16(aBL + 16, Bl + rb + 8);
        }
        cp_commit();
    }

    int cur = 0;
    for (int k0 = kbeg; k0 < kend; k0 += 32, cur ^= 1) {
        int nxt = cur ^ 1;
        int kn = k0 + 32;
        if (kn < kend) {
            uint32_t off = nxt * stB;
            size_t ra = (size_t)(bm + ldr) * lda + kn + lde16;
            cp_async16(aAH + off,      Ah + ra);
            cp_async16(aAH + off + 16, Ah + ra + 8);
            cp_async16(aAL + off,      Al + ra);
            cp_async16(aAL + off + 16, Al + ra + 8);
            if (bok) {
                size_t rb = (size_t)(bn + ldr) * ldb + kn + lde16;
                cp_async16(aBH + off,      Bh + rb);
                cp_async16(aBH + off + 16, Bh + rb + 8);
                cp_async16(aBL + off,      Bl + rb);
                cp_async16(aBL + off + 16, Bl + rb + 8);
            }
        }
        cp_commit();
        cp_wait1();
        __syncthreads();

        uint32_t so = cur * stB;

#pragma unroll
        for (int ks = 0; ks < 2; ks++) {
            uint32_t ko = so + ks * 32;   // 8 words per k-step

            uint32_t bh[4][2], bl[4][2];
            ldsm_x4(bh[0][0], bh[0][1], bh[1][0], bh[1][1], bBHf + ko);
            ldsm_x4(bh[2][0], bh[2][1], bh[3][0], bh[3][1], bBHf + ko + miStep);
            ldsm_x4(bl[0][0], bl[0][1], bl[1][0], bl[1][1], bBLf + ko);
            ldsm_x4(bl[2][0], bl[2][1], bl[3][0], bl[3][1], bBLf + ko + miStep);

#pragma unroll
            for (int mi = 0; mi < 4; mi++) {
                uint32_t ah0, ah1, ah2, ah3, al0, al1, al2, al3;
                ldsm_x4(ah0, ah1, ah2, ah3, bAHf + ko + mi * miStep);
                ldsm_x4(al0, al1, al2, al3, bALf + ko + mi * miStep);
#pragma unroll
                for (int ni = 0; ni < 4; ni++) {
                    mma_bf16(acc[mi][ni], ah0, ah1, ah2, ah3, bl[ni][0], bl[ni][1]);
                    mma_bf16(acc[mi][ni], al0, al1, al2, al3, bh[ni][0], bh[ni][1]);
                    mma_bf16(acc[mi][ni], ah0, ah1, ah2, ah3, bh[ni][0], bh[ni][1]);
                }
            }
        }
        __syncthreads();
    }

    // epilogue
#pragma unroll
    for (int mi = 0; mi < 4; mi++) {
#pragma unroll
        for (int ni = 0; ni < 4; ni++) {
            int r0 = bm + wm + mi * 16 + lq;
            int c0 = bn + wn + ni * 8 + 2 * lr4;
            if (c0 >= N) continue;
            if (mode == 1) {
                atomicAdd(&C[(size_t)r0 * ldc + c0],     acc[mi][ni][0]);
                atomicAdd(&C[(size_t)r0 * ldc + c0 + 1], acc[mi][ni][1]);
                atomicAdd(&C[(size_t)(r0 + 8) * ldc + c0],     acc[mi][ni][2]);
                atomicAdd(&C[(size_t)(r0 + 8) * ldc + c0 + 1], acc[mi][ni][3]);
            } else if (mode == 2) {
                float b0 = bias[c0], b1 = bias[c0 + 1];
                float v0 = acc[mi][ni][0] + b0, v1 = acc[mi][ni][1] + b1;
                float v2 = acc[mi][ni][2] + b0, v3 = acc[mi][ni][3] + b1;
                v0 = (v0 > 20.f) ? v0 : log1pf(expf(v0));
                v1 = (v1 > 20.f) ? v1 : log1pf(expf(v1));
                v2 = (v2 > 20.f) ? v2 : log1pf(expf(v2));
                v3 = (v3 > 20.f) ? v3 : log1pf(expf(v3));
                *(float2*)&C[(size_t)r0 * ldc + c0] = make_float2(v0, v1);
                *(float2*)&C[(size_t)(r0 + 8) * ldc + c0] = make_float2(v2, v3);
            } else {
                *(float2*)&C[(size_t)r0 * ldc + c0] = make_float2(acc[mi][ni][0], acc[mi][ni][1]);
                *(float2*)&C[(size_t)(r0 + 8) * ldc + c0] = make_float2(acc[mi][ni][2], acc[mi][ni][3]);
            }
        }
    }
}

// ---------------- pooling / PPM ----------------
__global__ void k_pool0_reduce(const float* __restrict__ g, const float* __restrict__ be,
                               const float* __restrict__ mu, const float* __restrict__ var)
{
    int o = blockIdx.x, b = blockIdx.y;
    float sc = g[o] * rsqrtf(var[o] + BN_EPS);
    float sh = be[o] - mu[o] * sc;
    float s = 0.f;
    for (int hw = threadIdx.x; hw < HW; hw += blockDim.x) {
        float v = g_t[(size_t)(b * HW + hw) * DIM + o] * sc + sh;
        v = fminf(fmaxf(v, 0.f), 6.f);
        s += v;
    }
    __shared__ float red[256];
    red[threadIdx.x] = s;
    __syncthreads();
    for (int st = 128; st > 0; st >>= 1) {
        if (threadIdx.x < st) red[threadIdx.x] += red[threadIdx.x + st];
        __syncthreads();
    }
    if (threadIdx.x == 0) g_y0[b * DIM + o] = red[0] * (1.f / (float)HW);
}

__global__ void k_bcast_y0() {
    int t = blockIdx.x * blockDim.x + threadIdx.x;
    if (t >= NB * HW * DIM) return;
    int o  = t % DIM;
    int hw = (t / DIM) % HW;
    int b  = t / (DIM * HW);
    split_store(g_y0[b * DIM + o], g_seq_h, g_seq_l,
                (size_t)(b * HW + hw) * D_MODEL + IN_CHS + o);
}

__global__ void k_avgpool(const float* __restrict__ x, float* __restrict__ out, int s) {
    int t = blockIdx.x * blockDim.x + threadIdx.x;
    int total = NB * IN_CHS * s * s;
    if (t >= total) return;
    int q = t % s;
    int p = (t / s) % s;
    int c = (t / (s * s)) % IN_CHS;
    int b = t / (s * s * IN_CHS);
    int hs = (p * 32) / s, he = ((p + 1) * 32 + s - 1) / s;
    int ws = (q * 32) / s, we = ((q + 1) * 32 + s - 1) / s;
    const float* xp = x + (size_t)(b * IN_CHS + c) * HW;
    float sum = 0.f;
    for (int h = hs; h < he; h++)
        for (int w = ws; w < we; w++) sum += xp[h * 32 + w];
    out[t] = sum / (float)((he - hs) * (we - ws));
}

__global__ void k_pconv(const float* __restrict__ pooled, float* __restrict__ outp,
                        const float* __restrict__ w,
                        const float* __restrict__ g, const float* __restrict__ be,
                        const float* __restrict__ mu, const float* __restrict__ var, int s)
{
    int ss = s * s;
    int pq = blockIdx.x % ss;
    int b  = blockIdx.x / ss;
    __shared__ float sv[IN_CHS];
    for (int c = threadIdx.x; c < IN_CHS; c += 128)
        sv[c] = pooled[(size_t)(b * IN_CHS + c) * ss + pq];
    __syncthreads();
    int o = threadIdx.x;
    const float* wr = w + (size_t)o * IN_CHS;
    float acc = 0.f;
#pragma unroll 8
    for (int c = 0; c < IN_CHS; c++) acc += __ldg(&wr[c]) * sv[c];
    float sc = g[o] * rsqrtf(var[o] + BN_EPS);
    float v = acc * sc + (be[o] - mu[o] * sc);
    v = fminf(fmaxf(v, 0.f), 6.f);
    outp[(size_t)(b * DIM + o) * ss + pq] = v;
}

__global__ void k_upsample(const float* __restrict__ yp, int s, int colbase) {
    int t = blockIdx.x * blockDim.x + threadIdx.x;
    if (t >= NB * DIM * HW) return;
    int o  = t % DIM;
    int hw = (t / DIM) % HW;
    int b  = t / (DIM * HW);
    int h = hw >> 5, w = hw & 31;
    float fs = (float)s;
    float sh_ = (h + 0.5f) * fs / 32.f - 0.5f;
    sh_ = fminf(fmaxf(sh_, 0.f), fs - 1.f);
    int i0h = (int)floorf(sh_);
    int i1h = min(i0h + 1, s - 1);
    float wh = sh_ - (float)i0h;
    float sw_ = (w + 0.5f) * fs / 32.f - 0.5f;
    sw_ = fminf(fmaxf(sw_, 0.f), fs - 1.f);
    int i0w = (int)floorf(sw_);
    int i1w = min(i0w + 1, s - 1);
    float ww = sw_ - (float)i0w;
    const float* yb = yp + (size_t)(b * DIM + o) * s * s;
    float v = (1.f - wh) * ((1.f - ww) * yb[i0h * s + i0w] + ww * yb[i0h * s + i1w])
            +        wh  * ((1.f - ww) * yb[i1h * s + i0w] + ww * yb[i1h * s + i1w]);
    split_store(v, g_seq_h, g_seq_l, (size_t)(b * HW + hw) * D_MODEL + colbase + o);
}

// ---------------- mamba elementwise ----------------
__global__ void k_conv1d(const float* __restrict__ cw, const float* __restrict__ cb) {
    int t = blockIdx.x * blockDim.x + threadIdx.x;
    if (t >= MROWS * D_INNER) return;
    int d = t % D_INNER;
    int m = t / D_INNER;
    int l = m % LSEQ;
    float acc = cb[d];
    const float* w4 = cw + d * 4;
#pragma unroll
    for (int j = 0; j < 4; j++) {
        int ll = l - 3 + j;
        if (ll >= 0) acc += w4[j] * g_xz[(size_t)(m + j - 3) * (2 * D_INNER) + d];
    }
    float uu = acc / (1.f + expf(-acc));
    g_u[t] = uu;
    split_store(uu, g_u_h, g_u_l, t);
}

__global__ void k_scan(const float* __restrict__ A_log, const float* __restrict__ Dp) {
    int t = blockIdx.x * blockDim.x + threadIdx.x;
    int lane = t & 31;
    int half = lane >> 4;
    int n = lane & 15;
    int pair = (t >> 5) * 2 + half;
    if (pair >= NB * D_INNER) return;
    int b = pair / D_INNER, d = pair % D_INNER;
    float Ac = -expf(A_log[d * D_STATE + n]);
    float Dd = Dp[d];
    float h = 0.f;
    int m0 = b * LSEQ;
    for (int l = 0; l < LSEQ; l++) {
        int m = m0 + l;
        float delta = g_delta[(size_t)m * D_INNER + d];
        float uu    = g_u[(size_t)m * D_INNER + d];
        float Bn    = g_xdbl[m * 96 + DT_RANK + n];
        float Cn    = g_xdbl[m * 96 + DT_RANK + D_STATE + n];
        h = expf(delta * Ac) * h + (delta * Bn) * uu;
        float p = h * Cn;
        p += __shfl_xor_sync(0xffffffffu, p, 1);
        p += __shfl_xor_sync(0xffffffffu, p, 2);
        p += __shfl_xor_sync(0xffffffffu, p, 4);
        p += __shfl_xor_sync(0xffffffffu, p, 8);
        if (n == 0) {
            float z = g_xz[(size_t)m * (2 * D_INNER) + D_INNER + d];
            float yv = (p + uu * Dd) * (z / (1.f + expf(-z)));
            split_store(yv, g_yg_h, g_yg_l, (size_t)m * D_INNER + d);
        }
    }
}

__global__ void k_out(float* __restrict__ out) {
    int t = blockIdx.x * blockDim.x + threadIdx.x;
    if (t >= NB * D_MODEL * HW) return;
    int hw = t % HW;
    int c  = (t / HW) % D_MODEL;
    int b  = t / (HW * D_MODEL);
    out[t] = g_yout[(size_t)(b * HW + hw) * D_MODEL + c];
}

// ---------------- launch ----------------
extern "C" void kernel_launch(void* const* d_in, const int* in_sizes, int n_in,
                              void* d_out, int out_size)
{
    const float* x        = (const float*)d_in[0];
    const float* pool_w   = (const float*)d_in[1];
    const float* bn_gamma = (const float*)d_in[2];
    const float* bn_beta  = (const float*)d_in[3];
    const float* bn_mean  = (const float*)d_in[4];
    const float* bn_var   = (const float*)d_in[5];
    const float* in_proj_w  = (const float*)d_in[6];
    const float* conv1d_w   = (const float*)d_in[7];
    const float* conv1d_b   = (const float*)d_in[8];
    const float* x_proj_w   = (const float*)d_in[9];
    const float* dt_proj_w  = (const float*)d_in[10];
    const float* dt_proj_b  = (const float*)d_in[11];
    const float* A_log      = (const float*)d_in[12];
    const float* Dp         = (const float*)d_in[13];
    const float* out_proj_w = (const float*)d_in[14];
    float* out = (float*)d_out;

    cudaFuncSetAttribute(k_gemm_tc, cudaFuncAttributeMaxDynamicSharedMemorySize, GEMM_SMEM);

    void* p;
    float *tbuf, *xz, *xdbl, *delta, *yout;
    float *pool9, *pool17, *pool25, *ppm9, *ppm17, *ppm25;
    uint16_t *seq_h, *seq_l, *u_h, *u_l, *xdbl_h, *xdbl_l, *yg_h, *yg_l;
    uint16_t *wip_h, *wip_l, *wxp_h, *wxp_l, *wdt_h, *wdt_l, *wop_h, *wop_l, *wp0_h, *wp0_l;
    cudaGetSymbolAddress(&p, g_t);      tbuf  = (float*)p;
    cudaGetSymbolAddress(&p, g_xz);     xz    = (float*)p;
    cudaGetSymbolAddress(&p, g_xdbl);   xdbl  = (float*)p;
    cudaGetSymbolAddress(&p, g_delta);  delta = (float*)p;
    cudaGetSymbolAddress(&p, g_yout);   yout  = (float*)p;
    cudaGetSymbolAddress(&p, g_pool9);  pool9 = (float*)p;
    cudaGetSymbolAddress(&p, g_pool17); pool17= (float*)p;
    cudaGetSymbolAddress(&p, g_pool25); pool25= (float*)p;
    cudaGetSymbolAddress(&p, g_ppm9);   ppm9  = (float*)p;
    cudaGetSymbolAddress(&p, g_ppm17);  ppm17 = (float*)p;
    cudaGetSymbolAddress(&p, g_ppm25);  ppm25 = (float*)p;
    cudaGetSymbolAddress(&p, g_seq_h);  seq_h = (uint16_t*)p;
    cudaGetSymbolAddress(&p, g_seq_l);  seq_l = (uint16_t*)p;
    cudaGetSymbolAddress(&p, g_u_h);    u_h   = (uint16_t*)p;
    cudaGetSymbolAddress(&p, g_u_l);    u_l   = (uint16_t*)p;
    cudaGetSymbolAddress(&p, g_xdbl_h); xdbl_h= (uint16_t*)p;
    cudaGetSymbolAddress(&p, g_xdbl_l); xdbl_l= (uint16_t*)p;
    cudaGetSymbolAddress(&p, g_yg_h);   yg_h  = (uint16_t*)p;
    cudaGetSymbolAddress(&p, g_yg_l);   yg_l  = (uint16_t*)p;
    cudaGetSymbolAddress(&p, g_wip_h);  wip_h = (uint16_t*)p;
    cudaGetSymbolAddress(&p, g_wip_l);  wip_l = (uint16_t*)p;
    cudaGetSymbolAddress(&p, g_wxp_h);  wxp_h = (uint16_t*)p;
    cudaGetSymbolAddress(&p, g_wxp_l);  wxp_l = (uint16_t*)p;
    cudaGetSymbolAddress(&p, g_wdt_h);  wdt_h = (uint16_t*)p;
    cudaGetSymbolAddress(&p, g_wdt_l);  wdt_l = (uint16_t*)p;
    cudaGetSymbolAddress(&p, g_wop_h);  wop_h = (uint16_t*)p;
    cudaGetSymbolAddress(&p, g_wop_l);  wop_l = (uint16_t*)p;
    cudaGetSymbolAddress(&p, g_wp0_h);  wp0_h = (uint16_t*)p;
    cudaGetSymbolAddress(&p, g_wp0_l);  wp0_l = (uint16_t*)p;

    int T;

    // weight split for pool0 + zero split-K accumulators
    T = DIM * IN_CHS;    k_split<<<(T + 255) / 256, 256>>>(pool_w, wp0_h, wp0_l, T);
    T = MROWS * DIM;     k_zero<<<(T + 255) / 256, 256>>>(tbuf, T);

    // x -> seq_h/l[:, 0:512]
    T = NB * HW * IN_CHS;
    k_x_to_seq<<<(T + 255) / 256, 256>>>(x);

    // 4th launch (6th overall) => the one ncu -s 5 -c 1 profiles
    // pool0: conv1x1 over full res (split-K=8, atomic)
    k_gemm_tc<<<dim3(1, 16, 8), 256, GEMM_SMEM>>>(MROWS, DIM, IN_CHS, 64, 1,
        seq_h, seq_l, D_MODEL, wp0_h, wp0_l, IN_CHS, tbuf, DIM, nullptr);
    k_pool0_reduce<<<dim3(DIM, NB), 256>>>(bn_gamma, bn_beta, bn_mean, bn_var);
    T = NB * HW * DIM;
    k_bcast_y0<<<(T + 255) / 256, 256>>>();

    // pool scales 9, 17, 25
    const int scales[3]  = {9, 17, 25};
    float* pls[3] = {pool9, pool17, pool25};
    float* pms[3] = {ppm9, ppm17, ppm25};
    for (int i = 0; i < 3; i++) {
        int s = scales[i];
        int li = i + 1;
        T = NB * IN_CHS * s * s;
        k_avgpool<<<(T + 255) / 256, 256>>>(x, pls[i], s);
        k_pconv<<<NB * s * s, 128>>>(pls[i], pms[i],
                                     pool_w + (size_t)li * DIM * IN_CHS,
                                     bn_gamma + li * DIM, bn_beta + li * DIM,
                                     bn_mean + li * DIM, bn_var + li * DIM, s);
        T = NB * DIM * HW;
        k_upsample<<<(T + 255) / 256, 256>>>(pms[i], s, IN_CHS + DIM * li);
    }

    // in_proj: xz = seq @ in_proj_w^T  [2048 x 4096] K=1024
    T = 2 * D_INNER * D_MODEL;
    k_split<<<(T + 255) / 256, 256>>>(in_proj_w, wip_h, wip_l, T);
    k_gemm_tc<<<dim3(32, 16, 1), 256, GEMM_SMEM>>>(MROWS, 2 * D_INNER, D_MODEL, D_MODEL, 0,
        seq_h, seq_l, D_MODEL, wip_h, wip_l, D_MODEL, xz, 2 * D_INNER, nullptr);

    // causal depthwise conv + SiLU -> u (+ split)
    T = MROWS * D_INNER;
    k_conv1d<<<(T + 255) / 256, 256>>>(conv1d_w, conv1d_b);

    // x_proj: x_dbl = u @ x_proj_w^T  [2048 x 96] K=2048, split-K=8 atomic
    T = 96 * D_INNER;
    k_split<<<(T + 255) / 256, 256>>>(x_proj_w, wxp_h, wxp_l, T);
    T = MROWS * 96;
    k_zero<<<(T + 255) / 256, 256>>>(xdbl, T);
    k_gemm_tc<<<dim3(1, 16, 8), 256, GEMM_SMEM>>>(MROWS, 96, D_INNER, 256, 1,
        u_h, u_l, D_INNER, wxp_h, wxp_l, D_INNER, xdbl, 96, nullptr);

    // split xdbl, split dt weights, dt_proj with fused bias+softplus
    T = MROWS * 96;
    k_split<<<(T + 255) / 256, 256>>>(xdbl, xdbl_h, xdbl_l, T);
    T = D_INNER * DT_RANK;
    k_split<<<(T + 255) / 256, 256>>>(dt_proj_w, wdt_h, wdt_l, T);
    k_gemm_tc<<<dim3(16, 16, 1), 256, GEMM_SMEM>>>(MROWS, D_INNER, DT_RANK, DT_RANK, 2,
        xdbl_h, xdbl_l, 96, wdt_h, wdt_l, DT_RANK, delta, D_INNER, dt_proj_b);

    // selective scan + gate (writes ygate hi/lo)
    k_scan<<<256, 256>>>(A_log, Dp);

    // out_proj: yout = ygate @ out_proj_w^T  [2048 x 1024] K=2048, split-K=2 atomic
    T = MROWS * D_MODEL;
    k_zero<<<(T + 255) / 256, 256>>>(yout, T);
    T = D_MODEL * D_INNER;
    k_split<<<(T + 255) / 256, 256>>>(out_proj_w, wop_h, wop_l, T);
    k_gemm_tc<<<dim3(8, 16, 2), 256, GEMM_SMEM>>>(MROWS, D_MODEL, D_INNER, 1024, 1,
        yg_h, yg_l, D_INNER, wop_h, wop_l, D_INNER, yout, D_MODEL, nullptr);

    // transpose to [B, D_MODEL, H, W]
    T = NB * D_MODEL * HW;
    k_out<<<(T + 255) / 256, 256>>>(out);
}

// round 17
// speedup vs baseline: 1.0123x; 1.0123x over previous
#include <cuda_runtime.h>
#include <cuda_bf16.h>
#include <math.h>
#include <stdint.h>

#define NB 2
#define HW 1024
#define LSEQ 1024
#define IN_CHS 512
#define DIM 128
#define D_MODEL 1024
#define D_INNER 2048
#define DT_RANK 64
#define D_STATE 16
#define MROWS (NB*LSEQ)
#define BN_EPS 1e-5f

// ---------------- scratch (allocation-free: device globals) ----------------
__device__ float g_t    [MROWS * DIM];
__device__ float g_y0   [NB * DIM];
__device__ float g_pool9 [NB*IN_CHS*81];
__device__ float g_pool17[NB*IN_CHS*289];
__device__ float g_pool25[NB*IN_CHS*625];
__device__ float g_ppm9 [NB*DIM*81];
__device__ float g_ppm17[NB*DIM*289];
__device__ float g_ppm25[NB*DIM*625];
__device__ float g_xz   [MROWS * 2*D_INNER];
__device__ float g_u    [MROWS * D_INNER];
__device__ float g_xdbl [MROWS * 96];
__device__ float g_delta[MROWS * D_INNER];
__device__ float g_yout [MROWS * D_MODEL];

// bf16 hi/lo pairs for GEMM operands (16B aligned for cp.async)
__device__ __align__(16) uint16_t g_seq_h  [MROWS * D_MODEL];
__device__ __align__(16) uint16_t g_seq_l  [MROWS * D_MODEL];
__device__ __align__(16) uint16_t g_u_h    [MROWS * D_INNER];
__device__ __align__(16) uint16_t g_u_l    [MROWS * D_INNER];
__device__ __align__(16) uint16_t g_xdbl_h [MROWS * 96];
__device__ __align__(16) uint16_t g_xdbl_l [MROWS * 96];
__device__ __align__(16) uint16_t g_yg_h   [MROWS * D_INNER];
__device__ __align__(16) uint16_t g_yg_l   [MROWS * D_INNER];
__device__ __align__(16) uint16_t g_wip_h  [2*D_INNER * D_MODEL];
__device__ __align__(16) uint16_t g_wip_l  [2*D_INNER * D_MODEL];
__device__ __align__(16) uint16_t g_wxp_h  [96 * D_INNER];
__device__ __align__(16) uint16_t g_wxp_l  [96 * D_INNER];
__device__ __align__(16) uint16_t g_wdt_h  [D_INNER * DT_RANK];
__device__ __align__(16) uint16_t g_wdt_l  [D_INNER * DT_RANK];
__device__ __align__(16) uint16_t g_wop_h  [D_MODEL * D_INNER];
__device__ __align__(16) uint16_t g_wop_l  [D_MODEL * D_INNER];
__device__ __align__(16) uint16_t g_wp0_h  [DIM * IN_CHS];
__device__ __align__(16) uint16_t g_wp0_l  [DIM * IN_CHS];

__device__ __forceinline__ void split_store(float v, uint16_t* hi, uint16_t* lo, size_t idx) {
    __nv_bfloat16 h = __float2bfloat16(v);
    hi[idx] = __bfloat16_as_ushort(h);
    lo[idx] = __bfloat16_as_ushort(__float2bfloat16(v - __bfloat162float(h)));
}

// ---------------- small helpers ----------------
__global__ void k_zero(float* p, int n) {
    int t = blockIdx.x * blockDim.x + threadIdx.x;
    if (t < n) p[t] = 0.f;
}

__global__ void k_split(const float* __restrict__ src, uint16_t* __restrict__ hi,
                        uint16_t* __restrict__ lo, int n) {
    int t = blockIdx.x * blockDim.x + threadIdx.x;
    if (t < n) split_store(src[t], hi, lo, t);
}

__global__ void k_x_to_seq(const float* __restrict__ x) {
    int t = blockIdx.x * blockDim.x + threadIdx.x;
    if (t >= NB * HW * IN_CHS) return;
    int c  = t % IN_CHS;
    int hw = (t / IN_CHS) % HW;
    int b  = t / (IN_CHS * HW);
    split_store(x[(size_t)(b * IN_CHS + c) * HW + hw], g_seq_h, g_seq_l,
                (size_t)(b * HW + hw) * D_MODEL + c);
}

// ---------------- tensor-core 3xBF16 GEMM (m16n8k16, ldmatrix, BK=32) ----------------
__device__ __forceinline__ void mma_bf16(float* c, uint32_t a0, uint32_t a1,
                                         uint32_t a2, uint32_t a3,
                                         uint32_t b0, uint32_t b1) {
    asm volatile(
        "mma.sync.aligned.m16n8k16.row.col.f32.bf16.bf16.f32 "
        "{%0,%1,%2,%3}, {%4,%5,%6,%7}, {%8,%9}, {%0,%1,%2,%3};\n"
        : "+f"(c[0]), "+f"(c[1]), "+f"(c[2]), "+f"(c[3])
        : "r"(a0), "r"(a1), "r"(a2), "r"(a3), "r"(b0), "r"(b1));
}
__device__ __forceinline__ void ldsm_x4(uint32_t& r0, uint32_t& r1, uint32_t& r2,
                                        uint32_t& r3, uint32_t addr) {
    asm volatile("ldmatrix.sync.aligned.m8n8.x4.shared.b16 {%0,%1,%2,%3}, [%4];"
                 : "=r"(r0), "=r"(r1), "=r"(r2), "=r"(r3) : "r"(addr));
}
__device__ __forceinline__ void cp_async16(uint32_t smem_addr, const void* gmem) {
    asm volatile("cp.async.cg.shared.global [%0], [%1], 16;\n" :: "r"(smem_addr), "l"(gmem));
}
__device__ __forceinline__ void cp_commit() { asm volatile("cp.async.commit_group;\n"); }
__device__ __forceinline__ void cp_wait1()  { asm volatile("cp.async.wait_group 1;\n"); }

// BK=32: per stage-operand tile 128 rows x 16 words (32 bf16) + 4 pad = 20 words/row
#define SMROW_W 20
#define TSZ_W (128 * SMROW_W)            // 2560 words = 10240 B per operand-stage
#define GEMM_SMEM (8 * TSZ_W * 4)        // 4 operands x 2 stages = 81920 B

// mode: 0 = plain store, 1 = atomicAdd, 2 = store softplus(acc + bias[col])
__global__ __launch_bounds__(256, 2)
void k_gemm_tc(int M, int N, int K, int kchunk, int mode,
               const uint16_t* __restrict__ Ah, const uint16_t* __restrict__ Al, int lda,
               const uint16_t* __restrict__ Bh, const uint16_t* __restrict__ Bl, int ldb,
               float* __restrict__ C, int ldc, const float* __restrict__ bias)
{
    extern __shared__ uint32_t smu[];
    uint32_t* AH = smu;
    uint32_t* AL = smu + 2 * TSZ_W;
    uint32_t* BH = smu + 4 * TSZ_W;
    uint32_t* BL = smu + 6 * TSZ_W;

    int bm = blockIdx.y * 128, bn = blockIdx.x * 128;
    int tid = threadIdx.x, lane = tid & 31, warp = tid >> 5;
    int wm = (warp >> 2) * 64;
    int wn = (warp & 3) * 32;
    int lq = lane >> 2;
    int lr4 = lane & 3;
    int kbeg = blockIdx.z * kchunk;
    int kend = min(K, kbeg + kchunk);

    float acc[4][4][4];
#pragma unroll
    for (int mi = 0; mi < 4; mi++)
#pragma unroll
        for (int ni = 0; ni < 4; ni++)
#pragma unroll
            for (int r = 0; r < 4; r++) acc[mi][ni][r] = 0.f;

    // loader: 2 threads per row; each covers 16 bf16 (2 x 16B chunks)
    int ldr   = tid >> 1;           // 0..127
    int lde16 = (tid & 1) * 16;     // element offset 0 or 16
    int ldw8  = (tid & 1) * 8;      // word offset 0 or 8
    bool bok = (bn + ldr) < N;

    if (!bok) {
#pragma unroll
        for (int st = 0; st < 2; st++)
#pragma unroll
            for (int i = 0; i < 8; i++) {
                BH[st * TSZ_W + ldr * SMROW_W + ldw8 + i] = 0u;
                BL[st * TSZ_W + ldr * SMROW_W + ldw8 + i] = 0u;
            }
    }
    __syncthreads();

    uint32_t aAH = (uint32_t)__cvta_generic_to_shared(&AH[ldr * SMROW_W + ldw8]);
    uint32_t aAL = (uint32_t)__cvta_generic_to_shared(&AL[ldr * SMROW_W + ldw8]);
    uint32_t aBH = (uint32_t)__cvta_generic_to_shared(&BH[ldr * SMROW_W + ldw8]);
    uint32_t aBL = (uint32_t)__cvta_generic_to_shared(&BL[ldr * SMROW_W + ldw8]);
    const uint32_t stB = TSZ_W * 4;          // stage stride in bytes

    // ldmatrix lane offsets (words, within a stage, k-chunk 0)
    int offA = (wm + (lane & 15)) * SMROW_W + ((lane & 16) >> 2);
    int offB = (wn + (lane & 7) + ((lane & 16) >> 1)) * SMROW_W + ((lane & 8) >> 1);

    uint32_t bAHf = (uint32_t)__cvta_generic_to_shared(AH) + offA * 4;
    uint32_t bALf = (uint32_t)__cvta_generic_to_shared(AL) + offA * 4;
    uint32_t bBHf = (uint32_t)__cvta_generic_to_shared(BH) + offB * 4;
    uint32_t bBLf = (uint32_t)__cvta_generic_to_shared(BL) + offB * 4;
    const uint32_t miStep = 16 * SMROW_W * 4;   // bytes per 16 rows

    // prologue: stage 0 (k = kbeg .. kbeg+32)
    {
        size_t ra = (size_t)(bm + ldr) * lda + kbeg + lde16;
        cp_async16(aAH,      Ah + ra);
        cp_async16(aAH + 16, Ah + ra + 8);
        cp_async16(aAL,      Al + ra);
        cp_async16(aAL + 16, Al + ra + 8);
        if (bok) {
            size_t rb = (size_t)(bn + ldr) * ldb + kbeg + lde16;
            cp_async16(aBH,      Bh + rb);
            cp_async16(aBH + 16, Bh + rb + 8);
            cp_async16(aBL,      Bl + rb);
            cp_async16(aBL + 16, Bl + rb + 8);
        }
        cp_commit();
    }

    int cur = 0;
    for (int k0 = kbeg; k0 < kend; k0 += 32, cur ^= 1) {
        int nxt = cur ^ 1;
        int kn = k0 + 32;
        if (kn < kend) {
            uint32_t off = nxt * stB;
            size_t ra = (size_t)(bm + ldr) * lda + kn + lde16;
            cp_async16(aAH + off,      Ah + ra);
            cp_async16(aAH + off + 16, Ah + ra + 8);
            cp_async16(aAL + off,      Al + ra);
            cp_async16(aAL + off + 16, Al + ra + 8);
            if (bok) {
                size_t rb = (size_t)(bn + ldr) * ldb + kn + lde16;
                cp_async16(aBH + off,      Bh + rb);
                cp_async16(aBH + off + 16, Bh + rb + 8);
                cp_async16(aBL + off,      Bl + rb);
                cp_async16(aBL + off + 16, Bl + rb + 8);
            }
        }
        cp_commit();
        cp_wait1();
        __syncthreads();

        uint32_t so = cur * stB;

#pragma unroll
        for (int ks = 0; ks < 2; ks++) {
            uint32_t ko = so + ks * 32;   // 8 words per k-step

            uint32_t bh[4][2], bl[4][2];
            ldsm_x4(bh[0][0], bh[0][1], bh[1][0], bh[1][1], bBHf + ko);
            ldsm_x4(bh[2][0], bh[2][1], bh[3][0], bh[3][1], bBHf + ko + miStep);
            ldsm_x4(bl[0][0], bl[0][1], bl[1][0], bl[1][1], bBLf + ko);
            ldsm_x4(bl[2][0], bl[2][1], bl[3][0], bl[3][1], bBLf + ko + miStep);

#pragma unroll
            for (int mi = 0; mi < 4; mi++) {
                uint32_t ah0, ah1, ah2, ah3, al0, al1, al2, al3;
                ldsm_x4(ah0, ah1, ah2, ah3, bAHf + ko + mi * miStep);
                ldsm_x4(al0, al1, al2, al3, bALf + ko + mi * miStep);
                // term-major: RAW reuse distance on each acc = 4 (was 1)
#pragma unroll
                for (int ni = 0; ni < 4; ni++)
                    mma_bf16(acc[mi][ni], ah0, ah1, ah2, ah3, bl[ni][0], bl[ni][1]);
#pragma unroll
                for (int ni = 0; ni < 4; ni++)
                    mma_bf16(acc[mi][ni], al0, al1, al2, al3, bh[ni][0], bh[ni][1]);
#pragma unroll
                for (int ni = 0; ni < 4; ni++)
                    mma_bf16(acc[mi][ni], ah0, ah1, ah2, ah3, bh[ni][0], bh[ni][1]);
            }
        }
        __syncthreads();
    }

    // epilogue
#pragma unroll
    for (int mi = 0; mi < 4; mi++) {
#pragma unroll
        for (int ni = 0; ni < 4; ni++) {
            int r0 = bm + wm + mi * 16 + lq;
            int c0 = bn + wn + ni * 8 + 2 * lr4;
            if (c0 >= N) continue;
            if (mode == 1) {
                atomicAdd(&C[(size_t)r0 * ldc + c0],     acc[mi][ni][0]);
                atomicAdd(&C[(size_t)r0 * ldc + c0 + 1], acc[mi][ni][1]);
                atomicAdd(&C[(size_t)(r0 + 8) * ldc + c0],     acc[mi][ni][2]);
                atomicAdd(&C[(size_t)(r0 + 8) * ldc + c0 + 1], acc[mi][ni][3]);
            } else if (mode == 2) {
                float b0 = bias[c0], b1 = bias[c0 + 1];
                float v0 = acc[mi][ni][0] + b0, v1 = acc[mi][ni][1] + b1;
                float v2 = acc[mi][ni][2] + b0, v3 = acc[mi][ni][3] + b1;
                v0 = (v0 > 20.f) ? v0 : log1pf(expf(v0));
                v1 = (v1 > 20.f) ? v1 : log1pf(expf(v1));
                v2 = (v2 > 20.f) ? v2 : log1pf(expf(v2));
                v3 = (v3 > 20.f) ? v3 : log1pf(expf(v3));
                *(float2*)&C[(size_t)r0 * ldc + c0] = make_float2(v0, v1);
                *(float2*)&C[(size_t)(r0 + 8) * ldc + c0] = make_float2(v2, v3);
            } else {
                *(float2*)&C[(size_t)r0 * ldc + c0] = make_float2(acc[mi][ni][0], acc[mi][ni][1]);
                *(float2*)&C[(size_t)(r0 + 8) * ldc + c0] = make_float2(acc[mi][ni][2], acc[mi][ni][3]);
            }
        }
    }
}

// ---------------- pooling / PPM ----------------
__global__ void k_pool0_reduce(const float* __restrict__ g, const float* __restrict__ be,
                               const float* __restrict__ mu, const float* __restrict__ var)
{
    int o = blockIdx.x, b = blockIdx.y;
    float sc = g[o] * rsqrtf(var[o] + BN_EPS);
    float sh = be[o] - mu[o] * sc;
    float s = 0.f;
    for (int hw = threadIdx.x; hw < HW; hw += blockDim.x) {
        float v = g_t[(size_t)(b * HW + hw) * DIM + o] * sc + sh;
        v = fminf(fmaxf(v, 0.f), 6.f);
        s += v;
    }
    __shared__ float red[256];
    red[threadIdx.x] = s;
    __syncthreads();
    for (int st = 128; st > 0; st >>= 1) {
        if (threadIdx.x < st) red[threadIdx.x] += red[threadIdx.x + st];
        __syncthreads();
    }
    if (threadIdx.x == 0) g_y0[b * DIM + o] = red[0] * (1.f / (float)HW);
}

__global__ void k_bcast_y0() {
    int t = blockIdx.x * blockDim.x + threadIdx.x;
    if (t >= NB * HW * DIM) return;
    int o  = t % DIM;
    int hw = (t / DIM) % HW;
    int b  = t / (DIM * HW);
    split_store(g_y0[b * DIM + o], g_seq_h, g_seq_l,
                (size_t)(b * HW + hw) * D_MODEL + IN_CHS + o);
}

__global__ void k_avgpool(const float* __restrict__ x, float* __restrict__ out, int s) {
    int t = blockIdx.x * blockDim.x + threadIdx.x;
    int total = NB * IN_CHS * s * s;
    if (t >= total) return;
    int q = t % s;
    int p = (t / s) % s;
    int c = (t / (s * s)) % IN_CHS;
    int b = t / (s * s * IN_CHS);
    int hs = (p * 32) / s, he = ((p + 1) * 32 + s - 1) / s;
    int ws = (q * 32) / s, we = ((q + 1) * 32 + s - 1) / s;
    const float* xp = x + (size_t)(b * IN_CHS + c) * HW;
    float sum = 0.f;
    for (int h = hs; h < he; h++)
        for (int w = ws; w < we; w++) sum += xp[h * 32 + w];
    out[t] = sum / (float)((he - hs) * (we - ws));
}

__global__ void k_pconv(const float* __restrict__ pooled, float* __restrict__ outp,
                        const float* __restrict__ w,
                        const float* __restrict__ g, const float* __restrict__ be,
                        const float* __restrict__ mu, const float* __restrict__ var, int s)
{
    int ss = s * s;
    int pq = blockIdx.x % ss;
    int b  = blockIdx.x / ss;
    __shared__ float sv[IN_CHS];
    for (int c = threadIdx.x; c < IN_CHS; c += 128)
        sv[c] = pooled[(size_t)(b * IN_CHS + c) * ss + pq];
    __syncthreads();
    int o = threadIdx.x;
    const float* wr = w + (size_t)o * IN_CHS;
    float acc = 0.f;
#pragma unroll 8
    for (int c = 0; c < IN_CHS; c++) acc += __ldg(&wr[c]) * sv[c];
    float sc = g[o] * rsqrtf(var[o] + BN_EPS);
    float v = acc * sc + (be[o] - mu[o] * sc);
    v = fminf(fmaxf(v, 0.f), 6.f);
    outp[(size_t)(b * DIM + o) * ss + pq] = v;
}

__global__ void k_upsample(const float* __restrict__ yp, int s, int colbase) {
    int t = blockIdx.x * blockDim.x + threadIdx.x;
    if (t >= NB * DIM * HW) return;
    int o  = t % DIM;
    int hw = (t / DIM) % HW;
    int b  = t / (DIM * HW);
    int h = hw >> 5, w = hw & 31;
    float fs = (float)s;
    float sh_ = (h + 0.5f) * fs / 32.f - 0.5f;
    sh_ = fminf(fmaxf(sh_, 0.f), fs - 1.f);
    int i0h = (int)floorf(sh_);
    int i1h = min(i0h + 1, s - 1);
    float wh = sh_ - (float)i0h;
    float sw_ = (w + 0.5f) * fs / 32.f - 0.5f;
    sw_ = fminf(fmaxf(sw_, 0.f), fs - 1.f);
    int i0w = (int)floorf(sw_);
    int i1w = min(i0w + 1, s - 1);
    float ww = sw_ - (float)i0w;
    const float* yb = yp + (size_t)(b * DIM + o) * s * s;
    float v = (1.f - wh) * ((1.f - ww) * yb[i0h * s + i0w] + ww * yb[i0h * s + i1w])
            +        wh  * ((1.f - ww) * yb[i1h * s + i0w] + ww * yb[i1h * s + i1w]);
    split_store(v, g_seq_h, g_seq_l, (size_t)(b * HW + hw) * D_MODEL + colbase + o);
}

// ---------------- mamba elementwise ----------------
__global__ void k_conv1d(const float* __restrict__ cw, const float* __restrict__ cb) {
    int t = blockIdx.x * blockDim.x + threadIdx.x;
    if (t >= MROWS * D_INNER) return;
    int d = t % D_INNER;
    int m = t / D_INNER;
    int l = m % LSEQ;
    float acc = cb[d];
    const float* w4 = cw + d * 4;
#pragma unroll
    for (int j = 0; j < 4; j++) {
        int ll = l - 3 + j;
        if (ll >= 0) acc += w4[j] * g_xz[(size_t)(m + j - 3) * (2 * D_INNER) + d];
    }
    float uu = acc / (1.f + expf(-acc));
    g_u[t] = uu;
    split_store(uu, g_u_h, g_u_l, t);
}

__global__ void k_scan(const float* __restrict__ A_log, const float* __restrict__ Dp) {
    int t = blockIdx.x * blockDim.x + threadIdx.x;
    int lane = t & 31;
    int half = lane >> 4;
    int n = lane & 15;
    int pair = (t >> 5) * 2 + half;
    if (pair >= NB * D_INNER) return;
    int b = pair / D_INNER, d = pair % D_INNER;
    float Ac = -expf(A_log[d * D_STATE + n]);
    float Dd = Dp[d];
    float h = 0.f;
    int m0 = b * LSEQ;
    for (int l = 0; l < LSEQ; l++) {
        int m = m0 + l;
        float delta = g_delta[(size_t)m * D_INNER + d];
        float uu    = g_u[(size_t)m * D_INNER + d];
        float Bn    = g_xdbl[m * 96 + DT_RANK + n];
        float Cn    = g_xdbl[m * 96 + DT_RANK + D_STATE + n];
        h = expf(delta * Ac) * h + (delta * Bn) * uu;
        float p = h * Cn;
        p += __shfl_xor_sync(0xffffffffu, p, 1);
        p += __shfl_xor_sync(0xffffffffu, p, 2);
        p += __shfl_xor_sync(0xffffffffu, p, 4);
        p += __shfl_xor_sync(0xffffffffu, p, 8);
        if (n == 0) {
            float z = g_xz[(size_t)m * (2 * D_INNER) + D_INNER + d];
            float yv = (p + uu * Dd) * (z / (1.f + expf(-z)));
            split_store(yv, g_yg_h, g_yg_l, (size_t)m * D_INNER + d);
        }
    }
}

__global__ void k_out(float* __restrict__ out) {
    int t = blockIdx.x * blockDim.x + threadIdx.x;
    if (t >= NB * D_MODEL * HW) return;
    int hw = t % HW;
    int c  = (t / HW) % D_MODEL;
    int b  = t / (HW * D_MODEL);
    out[t] = g_yout[(size_t)(b * HW + hw) * D_MODEL + c];
}

// ---------------- launch ----------------
extern "C" void kernel_launch(void* const* d_in, const int* in_sizes, int n_in,
                              void* d_out, int out_size)
{
    const float* x        = (const float*)d_in[0];
    const float* pool_w   = (const float*)d_in[1];
    const float* bn_gamma = (const float*)d_in[2];
    const float* bn_beta  = (const float*)d_in[3];
    const float* bn_mean  = (const float*)d_in[4];
    const float* bn_var   = (const float*)d_in[5];
    const float* in_proj_w  = (const float*)d_in[6];
    const float* conv1d_w   = (const float*)d_in[7];
    const float* conv1d_b   = (const float*)d_in[8];
    const float* x_proj_w   = (const float*)d_in[9];
    const float* dt_proj_w  = (const float*)d_in[10];
    const float* dt_proj_b  = (const float*)d_in[11];
    const float* A_log      = (const float*)d_in[12];
    const float* Dp         = (const float*)d_in[13];
    const float* out_proj_w = (const float*)d_in[14];
    float* out = (float*)d_out;

    cudaFuncSetAttribute(k_gemm_tc, cudaFuncAttributeMaxDynamicSharedMemorySize, GEMM_SMEM);

    void* p;
    float *tbuf, *xz, *xdbl, *delta, *yout;
    float *pool9, *pool17, *pool25, *ppm9, *ppm17, *ppm25;
    uint16_t *seq_h, *seq_l, *u_h, *u_l, *xdbl_h, *xdbl_l, *yg_h, *yg_l;
    uint16_t *wip_h, *wip_l, *wxp_h, *wxp_l, *wdt_h, *wdt_l, *wop_h, *wop_l, *wp0_h, *wp0_l;
    cudaGetSymbolAddress(&p, g_t);      tbuf  = (float*)p;
    cudaGetSymbolAddress(&p, g_xz);     xz    = (float*)p;
    cudaGetSymbolAddress(&p, g_xdbl);   xdbl  = (float*)p;
    cudaGetSymbolAddress(&p, g_delta);  delta = (float*)p;
    cudaGetSymbolAddress(&p, g_yout);   yout  = (float*)p;
    cudaGetSymbolAddress(&p, g_pool9);  pool9 = (float*)p;
    cudaGetSymbolAddress(&p, g_pool17); pool17= (float*)p;
    cudaGetSymbolAddress(&p, g_pool25); pool25= (float*)p;
    cudaGetSymbolAddress(&p, g_ppm9);   ppm9  = (float*)p;
    cudaGetSymbolAddress(&p, g_ppm17);  ppm17 = (float*)p;
    cudaGetSymbolAddress(&p, g_ppm25);  ppm25 = (float*)p;
    cudaGetSymbolAddress(&p, g_seq_h);  seq_h = (uint16_t*)p;
    cudaGetSymbolAddress(&p, g_seq_l);  seq_l = (uint16_t*)p;
    cudaGetSymbolAddress(&p, g_u_h);    u_h   = (uint16_t*)p;
    cudaGetSymbolAddress(&p, g_u_l);    u_l   = (uint16_t*)p;
    cudaGetSymbolAddress(&p, g_xdbl_h); xdbl_h= (uint16_t*)p;
    cudaGetSymbolAddress(&p, g_xdbl_l); xdbl_l= (uint16_t*)p;
    cudaGetSymbolAddress(&p, g_yg_h);   yg_h  = (uint16_t*)p;
    cudaGetSymbolAddress(&p, g_yg_l);   yg_l  = (uint16_t*)p;
    cudaGetSymbolAddress(&p, g_wip_h);  wip_h = (uint16_t*)p;
    cudaGetSymbolAddress(&p, g_wip_l);  wip_l = (uint16_t*)p;
    cudaGetSymbolAddress(&p, g_wxp_h);  wxp_h = (uint16_t*)p;
    cudaGetSymbolAddress(&p, g_wxp_l);  wxp_l = (uint16_t*)p;
    cudaGetSymbolAddress(&p, g_wdt_h);  wdt_h = (uint16_t*)p;
    cudaGetSymbolAddress(&p, g_wdt_l);  wdt_l = (uint16_t*)p;
    cudaGetSymbolAddress(&p, g_wop_h);  wop_h = (uint16_t*)p;
    cudaGetSymbolAddress(&p, g_wop_l);  wop_l = (uint16_t*)p;
    cudaGetSymbolAddress(&p, g_wp0_h);  wp0_h = (uint16_t*)p;
    cudaGetSymbolAddress(&p, g_wp0_l);  wp0_l = (uint16_t*)p;

    int T;

    // weight split for pool0 + zero split-K accumulators
    T = DIM * IN_CHS;    k_split<<<(T + 255) / 256, 256>>>(pool_w, wp0_h, wp0_l, T);
    T = MROWS * DIM;     k_zero<<<(T + 255) / 256, 256>>>(tbuf, T);

    // x -> seq_h/l[:, 0:512]
    T = NB * HW * IN_CHS;
    k_x_to_seq<<<(T + 255) / 256, 256>>>(x);

    // 4th launch (6th overall) => the one ncu -s 5 -c 1 profiles
    // pool0: conv1x1 over full res (split-K=8, atomic)
    k_gemm_tc<<<dim3(1, 16, 8), 256, GEMM_SMEM>>>(MROWS, DIM, IN_CHS, 64, 1,
        seq_h, seq_l, D_MODEL, wp0_h, wp0_l, IN_CHS, tbuf, DIM, nullptr);
    k_pool0_reduce<<<dim3(DIM, NB), 256>>>(bn_gamma, bn_beta, bn_mean, bn_var);
    T = NB * HW * DIM;
    k_bcast_y0<<<(T + 255) / 256, 256>>>();

    // pool scales 9, 17, 25
    const int scales[3]  = {9, 17, 25};
    float* pls[3] = {pool9, pool17, pool25};
    float* pms[3] = {ppm9, ppm17, ppm25};
    for (int i = 0; i < 3; i++) {
        int s = scales[i];
        int li = i + 1;
        T = NB * IN_CHS * s * s;
        k_avgpool<<<(T + 255) / 256, 256>>>(x, pls[i], s);
        k_pconv<<<NB * s * s, 128>>>(pls[i], pms[i],
                                     pool_w + (size_t)li * DIM * IN_CHS,
                                     bn_gamma + li * DIM, bn_beta + li * DIM,
                                     bn_mean + li * DIM, bn_var + li * DIM, s);
        T = NB * DIM * HW;
        k_upsample<<<(T + 255) / 256, 256>>>(pms[i], s, IN_CHS + DIM * li);
    }

    // in_proj: xz = seq @ in_proj_w^T  [2048 x 4096] K=1024
    T = 2 * D_INNER * D_MODEL;
    k_split<<<(T + 255) / 256, 256>>>(in_proj_w, wip_h, wip_l, T);
    k_gemm_tc<<<dim3(32, 16, 1), 256, GEMM_SMEM>>>(MROWS, 2 * D_INNER, D_MODEL, D_MODEL, 0,
        seq_h, seq_l, D_MODEL, wip_h, wip_l, D_MODEL, xz, 2 * D_INNER, nullptr);

    // causal depthwise conv + SiLU -> u (+ split)
    T = MROWS * D_INNER;
    k_conv1d<<<(T + 255) / 256, 256>>>(conv1d_w, conv1d_b);

    // x_proj: x_dbl = u @ x_proj_w^T  [2048 x 96] K=2048, split-K=8 atomic
    T = 96 * D_INNER;
    k_split<<<(T + 255) / 256, 256>>>(x_proj_w, wxp_h, wxp_l, T);
    T = MROWS * 96;
    k_zero<<<(T + 255) / 256, 256>>>(xdbl, T);
    k_gemm_tc<<<dim3(1, 16, 8), 256, GEMM_SMEM>>>(MROWS, 96, D_INNER, 256, 1,
        u_h, u_l, D_INNER, wxp_h, wxp_l, D_INNER, xdbl, 96, nullptr);

    // split xdbl, split dt weights, dt_proj with fused bias+softplus
    T = MROWS * 96;
    k_split<<<(T + 255) / 256, 256>>>(xdbl, xdbl_h, xdbl_l, T);
    T = D_INNER * DT_RANK;
    k_split<<<(T + 255) / 256, 256>>>(dt_proj_w, wdt_h, wdt_l, T);
    k_gemm_tc<<<dim3(16, 16, 1), 256, GEMM_SMEM>>>(MROWS, D_INNER, DT_RANK, DT_RANK, 2,
        xdbl_h, xdbl_l, 96, wdt_h, wdt_l, DT_RANK, delta, D_INNER, dt_proj_b);

    // selective scan + gate (writes ygate hi/lo)
    k_scan<<<256, 256>>>(A_log, Dp);

    // out_proj: yout = ygate @ out_proj_w^T  [2048 x 1024] K=2048, split-K=2 atomic
    T = MROWS * D_MODEL;
    k_zero<<<(T + 255) / 256, 256>>>(yout, T);
    T = D_MODEL * D_INNER;
    k_split<<<(T + 255) / 256, 256>>>(out_proj_w, wop_h, wop_l, T);
    k_gemm_tc<<<dim3(8, 16, 2), 256, GEMM_SMEM>>>(MROWS, D_MODEL, D_INNER, 1024, 1,
        yg_h, yg_l, D_INNER, wop_h, wop_l, D_INNER, yout, D_MODEL, nullptr);

    // transpose to [B, D_MODEL, H, W]
    T = NB * D_MODEL * HW;
    k_out<<<(T + 255) / 256, 256>>>(out);
}